// round 4
// baseline (speedup 1.0000x reference)
#include <cuda_runtime.h>
#include <cuda_bf16.h>

// -----------------------------------------------------------------------------
// FrustumSegmentationNet — collapsed exact-math (see R0 proof: FPS argmin always
// selects index 0 -> feats is the constant relu(be5)@Wd3^T + bd3; output is a
// per-pixel 6->80 linear + folded bias, zero outside the box).
//
// R4: prep folds Kinv + box offsets into per-channel (A,B,C) coefficients and
// emits a packed per-channel-pair blob; seg uses f32x2 packed FMA (FFMA2),
// incremental u-stepping, and a coalesced 2.5KB coefficient load per block.
// -----------------------------------------------------------------------------

#define HWPIX 65536
#define NCH   80
#define NPAIR 40

// Packed blob: per pair p (channels 2p, 2p+1), 8 float2 slots:
// [A, B, C'', w3, w4, w5, bias, pad]  (each float2 = (val_ch2p, val_ch2p+1))
__device__ float g_packf[NPAIR * 16];

// ---------------- f32x2 helpers ----------------
__device__ __forceinline__ unsigned long long pk2(float x) {
    unsigned long long r;
    asm("mov.b64 %0, {%1, %1};" : "=l"(r) : "f"(x));
    return r;
}
__device__ __forceinline__ unsigned long long fma2(unsigned long long a,
                                                   unsigned long long b,
                                                   unsigned long long c) {
    unsigned long long d;
    asm("fma.rn.f32x2 %0, %1, %2, %3;" : "=l"(d) : "l"(a), "l"(b), "l"(c));
    return d;
}
__device__ __forceinline__ unsigned long long add2(unsigned long long a,
                                                   unsigned long long b) {
    unsigned long long d;
    asm("add.rn.f32x2 %0, %1, %2;" : "=l"(d) : "l"(a), "l"(b));
    return d;
}
__device__ __forceinline__ void upk2(unsigned long long v, float& lo, float& hi) {
    asm("mov.b64 {%0, %1}, %2;" : "=f"(lo), "=f"(hi) : "l"(v));
}

// ---- prep: constant-feats fold + coefficient packing --------------------
__global__ __launch_bounds__(1024)
void frustum_prep_kernel(const float* __restrict__ be5,   // (256)
                         const float* __restrict__ Wd3,   // (128,256)
                         const float* __restrict__ bd3,   // (128)
                         const float* __restrict__ Ws,    // (80,134)
                         const float* __restrict__ bs,    // (80)
                         const float* __restrict__ intr,  // (3,3)
                         const int*   __restrict__ box)   // (5)
{
    __shared__ float sbe[256];
    __shared__ float sfc[128];
    __shared__ float sB[NCH];
    __shared__ float sK[9];
    __shared__ float soff[2];   // (0.5 - y1), (0.5 - x1)

    const int t    = threadIdx.x;
    const int warp = t >> 5;
    const int lane = t & 31;

    if (t < 256) sbe[t] = fmaxf(be5[t], 0.0f);
    if (t == 0) {
        float a = intr[0], b = intr[1], c = intr[2];
        float d = intr[3], e = intr[4], f = intr[5];
        float g = intr[6], h = intr[7], i9 = intr[8];
        float det = a * (e * i9 - f * h) - b * (d * i9 - f * g) + c * (d * h - e * g);
        float inv = 1.0f / det;
        sK[0] = (e * i9 - f * h) * inv; sK[1] = (c * h - b * i9) * inv; sK[2] = (b * f - c * e) * inv;
        sK[3] = (f * g - d * i9) * inv; sK[4] = (a * i9 - c * g) * inv; sK[5] = (c * d - a * f) * inv;
        sK[6] = (d * h - e * g) * inv;  sK[7] = (b * g - a * h) * inv;  sK[8] = (a * e - b * d) * inv;
        soff[0] = 0.5f - (float)box[1];  // u offset (col - y1 + 0.5)
        soff[1] = 0.5f - (float)box[0];  // v offset (row - x1 + 0.5)
    }
    __syncthreads();

    // Phase 1: fc[j] = bd3[j] + sum_k relu(be5[k]) * Wd3[j,k]; warp per row.
    for (int j = warp; j < 128; j += 32) {
        const float4* row = reinterpret_cast<const float4*>(Wd3 + j * 256);
        float4 a = row[lane];
        float4 b = row[lane + 32];
        int k0 = 4 * lane, k1 = 128 + 4 * lane;
        float s = a.x * sbe[k0]     + a.y * sbe[k0 + 1]
                + a.z * sbe[k0 + 2] + a.w * sbe[k0 + 3]
                + b.x * sbe[k1]     + b.y * sbe[k1 + 1]
                + b.z * sbe[k1 + 2] + b.w * sbe[k1 + 3];
        #pragma unroll
        for (int off = 16; off > 0; off >>= 1)
            s += __shfl_down_sync(0xFFFFFFFFu, s, off);
        if (lane == 0) sfc[j] = bd3[j] + s;
    }
    __syncthreads();

    // Phase 2: adjB[c] = bs[c] + fc . Ws[c, 6:]; warp per channel.
    for (int c = warp; c < NCH; c += 32) {
        const float* wsr = Ws + c * 134 + 6;
        float s = 0.0f;
        #pragma unroll
        for (int j = lane; j < 128; j += 32)
            s += sfc[j] * wsr[j];
        #pragma unroll
        for (int off = 16; off > 0; off >>= 1)
            s += __shfl_down_sync(0xFFFFFFFFu, s, off);
        if (lane == 0) sB[c] = bs[c] + s;
    }
    __syncthreads();

    // Phase 3: per-channel coefficients, packed by pair.
    if (t < NCH) {
        float w0 = Ws[t * 134 + 0], w1 = Ws[t * 134 + 1], w2 = Ws[t * 134 + 2];
        float w3 = Ws[t * 134 + 3], w4 = Ws[t * 134 + 4], w5 = Ws[t * 134 + 5];
        float A = w0 * sK[0] + w1 * sK[3] + w2 * sK[6];
        float B = w0 * sK[1] + w1 * sK[4] + w2 * sK[7];
        float C = w0 * sK[2] + w1 * sK[5] + w2 * sK[8];
        float Cpp = C + A * soff[0] + B * soff[1];
        int p = t >> 1, h = t & 1;
        float* dst = g_packf + p * 16;
        dst[0 * 2 + h] = A;
        dst[1 * 2 + h] = B;
        dst[2 * 2 + h] = Cpp;
        dst[3 * 2 + h] = w3;
        dst[4 * 2 + h] = w4;
        dst[5 * 2 + h] = w5;
        dst[6 * 2 + h] = sB[t];
        dst[7 * 2 + h] = 0.0f;
    }
}

// ---- seg: thread = (channel-group of 8 = 4 pairs, pixel quad) ------------
__global__ __launch_bounds__(128)
void frustum_seg_kernel(const float* __restrict__ rgb,    // (H,W,3)
                        const float* __restrict__ depth,  // (H,W)
                        const int*   __restrict__ box,    // (5)
                        float* __restrict__ out)          // (80,H,W)
{
    __shared__ float sP[NPAIR * 16];   // packed coefficient blob (2560 B)
    __shared__ int   sbox[4];

    const int t = threadIdx.x;
    #pragma unroll
    for (int i = t; i < NPAIR * 4; i += 128)   // 160 float4 loads
        reinterpret_cast<float4*>(sP)[i] =
            reinterpret_cast<const float4*>(g_packf)[i];
    if (t < 4) sbox[t] = box[t];
    __syncthreads();

    const int idx = blockIdx.x * 128 + t;    // 0 .. 163839
    const int g   = idx >> 14;               // channel group 0..9
    const int q   = idx & 16383;             // pixel quad
    const int p0  = q * 4;

    const int x1 = sbox[0], y1 = sbox[1], x2 = sbox[2], y2 = sbox[3];
    const int r   = p0 >> 8;    // row (shared by whole quad)
    const int cc0 = p0 & 255;   // first col

    // inputs (16B-aligned vector loads)
    float4 dz = *reinterpret_cast<const float4*>(depth + p0);
    const float4* rp = reinterpret_cast<const float4*>(rgb + (size_t)p0 * 3);
    float4 q0 = rp[0], q1 = rp[1], q2 = rp[2];
    float rg[12] = {q0.x, q0.y, q0.z, q0.w, q1.x, q1.y, q1.z, q1.w,
                    q2.x, q2.y, q2.z, q2.w};

    const bool rowin  = (r >= x1) && (r < x2);
    bool ins[4];
    #pragma unroll
    for (int i = 0; i < 4; i++)
        ins[i] = rowin && (cc0 + i >= y1) && (cc0 + i < y2);
    const bool allin = ins[0] & ins[1] & ins[2] & ins[3];

    // packed per-pixel operands
    unsigned long long u0p = pk2((float)cc0);
    unsigned long long vp  = pk2((float)r);
    unsigned long long zp[4] = {pk2(dz.x), pk2(dz.y), pk2(dz.z), pk2(dz.w)};
    unsigned long long rp2[4], gp2[4], bp2[4];
    #pragma unroll
    for (int i = 0; i < 4; i++) {
        rp2[i] = pk2(rg[i * 3 + 0]);
        gp2[i] = pk2(rg[i * 3 + 1]);
        bp2[i] = pk2(rg[i * 3 + 2]);
    }

    float* outbase = out + (size_t)g * 8 * HWPIX + p0;

    #pragma unroll
    for (int pp = 0; pp < 4; pp++) {
        const unsigned long long* cf =
            reinterpret_cast<const unsigned long long*>(sP + (g * 4 + pp) * 16);
        unsigned long long A2 = cf[0], B2 = cf[1], C2 = cf[2];
        unsigned long long w3 = cf[3], w4 = cf[4], w5 = cf[5], bi = cf[6];

        // t_i = A*u_i + B*v + C''   (u increments by 1 across the quad)
        unsigned long long t0 = fma2(A2, u0p, fma2(B2, vp, C2));
        unsigned long long t1 = add2(t0, A2);
        unsigned long long t2 = add2(t1, A2);
        unsigned long long t3 = add2(t2, A2);
        unsigned long long tv[4] = {t0, t1, t2, t3};

        float lo[4], hi[4];
        #pragma unroll
        for (int i = 0; i < 4; i++) {
            unsigned long long d =
                fma2(w3, rp2[i], fma2(w4, gp2[i], fma2(w5, bp2[i], bi)));
            unsigned long long s = fma2(zp[i], tv[i], d);
            upk2(s, lo[i], hi[i]);
        }
        if (!allin) {
            #pragma unroll
            for (int i = 0; i < 4; i++) {
                lo[i] = ins[i] ? lo[i] : 0.0f;
                hi[i] = ins[i] ? hi[i] : 0.0f;
            }
        }
        float4 olo = {lo[0], lo[1], lo[2], lo[3]};
        float4 ohi = {hi[0], hi[1], hi[2], hi[3]};
        *reinterpret_cast<float4*>(outbase + (size_t)(2 * pp) * HWPIX)     = olo;
        *reinterpret_cast<float4*>(outbase + (size_t)(2 * pp + 1) * HWPIX) = ohi;
    }
}

extern "C" void kernel_launch(void* const* d_in, const int* in_sizes, int n_in,
                              void* d_out, int out_size)
{
    const float* rgb   = (const float*)d_in[0];
    const float* depth = (const float*)d_in[1];
    const float* intr  = (const float*)d_in[2];
    const int*   box   = (const int*)  d_in[3];
    const float* be5   = (const float*)d_in[23];
    const float* Wd3   = (const float*)d_in[24];
    const float* bd3   = (const float*)d_in[25];
    const float* Ws    = (const float*)d_in[26];
    const float* bs    = (const float*)d_in[27];
    float* out = (float*)d_out;

    frustum_prep_kernel<<<1, 1024>>>(be5, Wd3, bd3, Ws, bs, intr, box);
    // 16384 quads * 10 groups = 163840 threads = 1280 blocks * 128
    frustum_seg_kernel<<<1280, 128>>>(rgb, depth, box, out);
}